// round 15
// baseline (speedup 1.0000x reference)
#include <cuda_runtime.h>
#include <cstdint>

#define BS 16
#define SS 2048
#define HH 1024
#define DD 32
#define CC 8
#define LL 3
#define NSPAN (BS * DD)     // 512
#define NBLK  (NSPAN * 2)   // 1024 — two half-span blocks per span

// L2 pin policy: first 96MB of enc evict_last (proven R11/R13), rest evict_first.
#define PIN_BYTES (96ull * 1024 * 1024)

#define STAGE_BYTES  8192            // 2 rows per stage
#define STAGE_FLOATS (STAGE_BYTES / 4)
#define NBUF 4                       // smem ring depth (4 stages in flight)

// partial logits per block (block = 2*span + half), rewritten every launch
__device__ float g_part[NBLK * LL];
// completion counter for last-block-done combine (reset by the tail block)
__device__ unsigned int g_count = 0;

__device__ __forceinline__ int load_int(const void* p, int i, bool is64) {
    if (is64) return (int)((const long long*)p)[i];
    return ((const int*)p)[i];
}

__device__ __forceinline__ unsigned int atom_add_release_gpu(unsigned int* p, unsigned int v) {
    unsigned int prev;
    asm volatile("atom.add.release.gpu.global.u32 %0, [%1], %2;"
                 : "=r"(prev) : "l"(p), "r"(v) : "memory");
    return prev;
}

__device__ __forceinline__ float ldcg_f(const float* p) {
    float v;
    asm volatile("ld.global.cg.f32 %0, [%1];" : "=f"(v) : "l"(p) : "memory");
    return v;
}

__device__ __forceinline__ void mbar_init(uint32_t a, uint32_t n) {
    asm volatile("mbarrier.init.shared.b64 [%0], %1;" :: "r"(a), "r"(n) : "memory");
}
__device__ __forceinline__ void mbar_expect_tx(uint32_t a, uint32_t bytes) {
    asm volatile("mbarrier.arrive.expect_tx.shared.b64 _, [%0], %1;"
                 :: "r"(a), "r"(bytes) : "memory");
}
__device__ __forceinline__ void mbar_wait(uint32_t a, uint32_t phase) {
    asm volatile(
        "{\n\t"
        ".reg .pred P;\n"
        "WAIT_%=:\n\t"
        "mbarrier.try_wait.parity.acquire.cta.shared::cta.b64 P, [%0], %1, 0x989680;\n\t"
        "@!P bra WAIT_%=;\n\t"
        "}"
        :: "r"(a), "r"(phase) : "memory");
}
// bulk async copy global->shared with L2 cache-policy hint
__device__ __forceinline__ void bulk_g2s(uint32_t dst, const void* src,
                                         uint32_t bytes, uint32_t mbar, uint64_t pol) {
    asm volatile(
        "cp.async.bulk.shared::cta.global.mbarrier::complete_tx::bytes.L2::cache_hint "
        "[%0], [%1], %2, [%3], %4;"
        :: "r"(dst), "l"(src), "r"(bytes), "r"(mbar), "l"(pol) : "memory");
}

__global__ void __launch_bounds__(256)
fused_kernel(const float* __restrict__ enc,
             const float* __restrict__ W,
             const float* __restrict__ bias,
             const void* __restrict__ headp,
             const void* __restrict__ tailp,
             const void* __restrict__ dtp,
             const void* __restrict__ labp,
             float* __restrict__ d_out, int out_size)
{
    __shared__ __align__(128) float s_stage[NBUF][STAGE_FLOATS];   // 32 KB ring
    __shared__ __align__(8)  unsigned long long s_mbar[NBUF];
    __shared__ int   s_flags;
    __shared__ float sred[8][3];

    const int blk  = blockIdx.x;
    const int span = blk >> 1;
    const int half = blk & 1;
    const int t    = threadIdx.x;      // 0..255

    // ---- init mbarriers + parallel int32-vs-int64 layout detection ----
    if (t == 0) {
        s_flags = 0;
        #pragma unroll
        for (int s = 0; s < NBUF; s++)
            mbar_init((uint32_t)__cvta_generic_to_shared(&s_mbar[s]), 1);
        asm volatile("fence.proxy.async.shared::cta;" ::: "memory");
    }
    __syncthreads();
    {
        const int w = 2 * t + 1;       // odd words 1..511
        int f = 0;
        if (((const int*)headp)[w]) f |= 1;
        if (((const int*)tailp)[w]) f |= 2;
        if (((const int*)dtp)[w])   f |= 4;
        if (((const int*)labp)[w])  f |= 8;
        if (f) atomicOr(&s_flags, f);
    }
    __syncthreads();
    const int flags = s_flags;
    const bool h64 = !(flags & 1);
    const bool t64 = !(flags & 2);
    const bool c64 = !(flags & 4);
    const bool l64 = !(flags & 8);

    const int s0 = load_int(headp, span, h64) + 1;     // mask starts at head+1
    const int n  = load_int(tailp, span, t64) - s0;    // typically 63
    const int c  = load_int(dtp,   span, c64);
    const int b  = span / DD;

    // this half's row range (region is CONTIGUOUS: nr*HH floats)
    const int hn = (n + 1) >> 1;
    const int r0 = half * hn;
    const int r1 = (r0 + hn < n) ? (r0 + hn) : n;
    const int nr = r1 - r0;

    const size_t elem_base = ((size_t)b * SS + (size_t)(s0 + r0)) * HH;
    const char* rb = (const char*)(enc + elem_base);
    const uint32_t total_bytes = (uint32_t)nr * (HH * 4);
    const int nstages = (int)((total_bytes + STAGE_BYTES - 1) / STAGE_BYTES);

    const bool pin = (elem_base * 4 + (size_t)total_bytes) <= PIN_BYTES;

    // cache policy for the bulk copies (created by producer thread)
    uint64_t pol = 0;
    if (t == 0) {
        if (pin) asm volatile("createpolicy.fractional.L2::evict_last.b64 %0;"  : "=l"(pol));
        else     asm volatile("createpolicy.fractional.L2::evict_first.b64 %0;" : "=l"(pol));
        // prologue: fill ALL NBUF buffers (stage q -> buffer q&3)
        const int pre = (nstages < NBUF) ? nstages : NBUF;
        for (int q = 0; q < pre; q++) {
            const uint32_t mb = (uint32_t)__cvta_generic_to_shared(&s_mbar[q]);
            const uint32_t bytes =
                (total_bytes - (uint32_t)q * STAGE_BYTES < STAGE_BYTES)
                    ? (total_bytes - (uint32_t)q * STAGE_BYTES) : STAGE_BYTES;
            mbar_expect_tx(mb, bytes);
            bulk_g2s((uint32_t)__cvta_generic_to_shared(&s_stage[q][0]),
                     rb + (size_t)q * STAGE_BYTES, bytes, mb, pol);
        }
    }

    // ---- consume stages: thread t owns columns [4t, 4t+4) ----
    // Stage q lives in buffer q&3; buffer's k-th use (k = q>>2) has phase k&1.
    // Refill distance is exactly NBUF so buffer/stage indices stay aligned.
    float a0 = 0.f, a1 = 0.f, a2 = 0.f, a3 = 0.f;
    const int total_floats = (int)(total_bytes >> 2);
    for (int q = 0; q < nstages; q++) {
        const int buf = q & (NBUF - 1);
        const uint32_t ph = (uint32_t)((q >> 2) & 1);
        mbar_wait((uint32_t)__cvta_generic_to_shared(&s_mbar[buf]), ph);

        const int base_f = q * STAGE_FLOATS;
        const int floats_this = (total_floats - base_f < STAGE_FLOATS)
                                    ? (total_floats - base_f) : STAGE_FLOATS;
        const float* sp = &s_stage[buf][0];
        // lane-contiguous 16B reads: conflict-free LDS.128
        for (int j = 4 * t; j < floats_this; j += 1024) {
            const float4 v = *(const float4*)(sp + j);
            a0 += v.x; a1 += v.y; a2 += v.z; a3 += v.w;
        }
        __syncthreads();               // everyone done reading buf
        if (t == 0 && q + NBUF < nstages) {
            const int qq = q + NBUF;   // same buffer slot, next phase
            const uint32_t mb = (uint32_t)__cvta_generic_to_shared(&s_mbar[buf]);
            const uint32_t bytes =
                (total_bytes - (uint32_t)qq * STAGE_BYTES < STAGE_BYTES)
                    ? (total_bytes - (uint32_t)qq * STAGE_BYTES) : STAGE_BYTES;
            mbar_expect_tx(mb, bytes);
            bulk_g2s((uint32_t)__cvta_generic_to_shared(&s_stage[buf][0]),
                     rb + (size_t)qq * STAGE_BYTES, bytes, mb, pol);
        }
    }

    // partial GEMV against W[c]: thread's 4 columns (un-normalized — linear)
    const float* Wc = W + (size_t)c * HH * LL + (size_t)(4 * t) * LL;
    float l0 = a0 * __ldg(&Wc[0]) + a1 * __ldg(&Wc[3]) + a2 * __ldg(&Wc[6]) + a3 * __ldg(&Wc[9]);
    float l1 = a0 * __ldg(&Wc[1]) + a1 * __ldg(&Wc[4]) + a2 * __ldg(&Wc[7]) + a3 * __ldg(&Wc[10]);
    float l2 = a0 * __ldg(&Wc[2]) + a1 * __ldg(&Wc[5]) + a2 * __ldg(&Wc[8]) + a3 * __ldg(&Wc[11]);

    #pragma unroll
    for (int o = 16; o > 0; o >>= 1) {
        l0 += __shfl_down_sync(0xffffffffu, l0, o);
        l1 += __shfl_down_sync(0xffffffffu, l1, o);
        l2 += __shfl_down_sync(0xffffffffu, l2, o);
    }
    {
        const int w = t >> 5, lane = t & 31;
        if (lane == 0) { sred[w][0] = l0; sred[w][1] = l1; sred[w][2] = l2; }
    }
    __syncthreads();

    if (t < LL) {
        float s = 0.f;
        #pragma unroll
        for (int k = 0; k < 8; k++) s += sred[k][t];
        g_part[blk * LL + t] = s;
    }

    // ---- last-block-done election: release atomic, one acquire fence total ----
    __shared__ int s_last;
    __syncthreads();                   // t<3 g_part stores ordered before release
    if (t == 0) {
        unsigned int prev = atom_add_release_gpu(&g_count, 1u);
        s_last = (prev == NBLK - 1) ? 1 : 0;
        if (s_last) {
            g_count = 0;               // reset for next graph replay
            __threadfence();           // acquire side — paid ONCE, by one block
        }
    }
    __syncthreads();
    if (!s_last) return;

    // ---- Phase 2: combine + loss (one block, 256 threads, 2 spans each) ----
    float nll = 0.f, vf = 0.f;
    #pragma unroll
    for (int k = 0; k < 2; k++) {
        const int sp = t + k * 256;    // span 0..511

        const int ss0 = load_int(headp, sp, h64) + 1;
        const int sn  = load_int(tailp, sp, t64) - ss0;
        const int sc  = load_int(dtp,   sp, c64);
        const int lab = load_int(labp,  sp, l64);

        const float inv = 1.0f / (float)sn;
        const float x0 = (ldcg_f(&g_part[(2 * sp) * LL + 0]) + ldcg_f(&g_part[(2 * sp + 1) * LL + 0])) * inv + __ldg(&bias[sc * LL + 0]);
        const float x1 = (ldcg_f(&g_part[(2 * sp) * LL + 1]) + ldcg_f(&g_part[(2 * sp + 1) * LL + 1])) * inv + __ldg(&bias[sc * LL + 1]);
        const float x2 = (ldcg_f(&g_part[(2 * sp) * LL + 2]) + ldcg_f(&g_part[(2 * sp + 1) * LL + 2])) * inv + __ldg(&bias[sc * LL + 2]);

        if (out_size >= NSPAN * LL) {
            d_out[sp * LL + 0] = x0;
            d_out[sp * LL + 1] = x1;
            d_out[sp * LL + 2] = x2;
        }

        const float m   = fmaxf(x0, fmaxf(x1, x2));
        const float lse = m + logf(expf(x0 - m) + expf(x1 - m) + expf(x2 - m));
        const bool valid = (lab >= 0);
        const float xl = valid ? ((lab == 0) ? x0 : ((lab == 1) ? x1 : x2)) : 0.f;
        nll += valid ? (lse - xl) : 0.f;
        vf  += valid ? 1.f : 0.f;
    }

    #pragma unroll
    for (int o = 16; o > 0; o >>= 1) {
        nll += __shfl_down_sync(0xffffffffu, nll, o);
        vf  += __shfl_down_sync(0xffffffffu, vf,  o);
    }
    __shared__ float s_n[8], s_v[8];
    const int w = t >> 5, lane = t & 31;
    if (lane == 0) { s_n[w] = nll; s_v[w] = vf; }
    __syncthreads();
    if (t == 0) {
        float a = 0.f, v = 0.f;
        #pragma unroll
        for (int k = 0; k < 8; k++) { a += s_n[k]; v += s_v[k]; }
        const float loss = a / v;
        if (out_size >= NSPAN * LL + 1)  d_out[NSPAN * LL] = loss;
        else if (out_size < NSPAN * LL)  d_out[0] = loss;
    }
}

extern "C" void kernel_launch(void* const* d_in, const int* in_sizes, int n_in,
                              void* d_out, int out_size)
{
    const float* enc  = (const float*)d_in[0];   // encoder_layer (BS,S,H) f32
    const float* W    = (const float*)d_in[1];   // (C,H,L) f32
    const float* bias = (const float*)d_in[2];   // (C,L)   f32
    const void*  head = d_in[3];                 // (BS,D) int32 or int64
    const void*  tail = d_in[4];
    const void*  dtid = d_in[5];
    const void*  labs = d_in[6];

    fused_kernel<<<NBLK, 256>>>(enc, W, bias, head, tail, dtid, labs,
                                (float*)d_out, out_size);
}